// round 2
// baseline (speedup 1.0000x reference)
#include <cuda_runtime.h>
#include <math.h>

#define FULL 0xffffffffu
typedef unsigned long long u64;

// ---------------- f32x2 helpers ----------------
__device__ __forceinline__ u64 pk2(float lo, float hi) {
    u64 r; asm("mov.b64 %0,{%1,%2};" : "=l"(r) : "f"(lo), "f"(hi)); return r;
}
__device__ __forceinline__ void upk2(u64 v, float& lo, float& hi) {
    asm("mov.b64 {%0,%1},%2;" : "=f"(lo), "=f"(hi) : "l"(v));
}
__device__ __forceinline__ u64 fma2(u64 a, u64 b, u64 c) {
    u64 d; asm("fma.rn.f32x2 %0,%1,%2,%3;" : "=l"(d) : "l"(a), "l"(b), "l"(c)); return d;
}
__device__ __forceinline__ u64 mul2(u64 a, u64 b) {
    u64 d; asm("mul.rn.f32x2 %0,%1,%2;" : "=l"(d) : "l"(a), "l"(b)); return d;
}
__device__ __forceinline__ u64 neg2(u64 a) { return a ^ 0x8000000080000000ull; }

// pack-index helpers: slots 0..7 over register bits {0,1,2} (= index bits 5,6,7).
// With pack bit PB, packed reg p holds slots (base, base|1<<PB), base = expnd(PB,p).
__host__ __device__ constexpr int pidx(int pb, int s) {           // s has bit pb == 0
    return ((s >> (pb + 1)) << pb) | (s & ((1 << pb) - 1));
}
__host__ __device__ constexpr int expnd(int pb, int p) {          // insert 0 at bit pb
    return ((p >> pb) << (pb + 1)) | (p & ((1 << pb) - 1));
}

// ---------------- coefficients ----------------
// Per fused block (RZ(c) -> RY(t) -> CNOT -> RY(t)), block-diagonal over control:
//  c=0: real rotation by sigma=(t1+t2)/2 (global phase dropped)
//  c=1: e^{i t0} * [[-sin d, cos d],[cos d, sin d]], d=(t2-t1)/2 -> a=e^{it0}cos d, b=e^{it0}sin d
// stored duplicated as f32x2: [cs, ss, ar, ai, br, bi]
__device__ u64 g_coef[21 * 6];

__global__ void setup_coef(const float* __restrict__ conv,
                           const float* __restrict__ pool) {
    int t = threadIdx.x;
    if (t >= 21) return;
    float t0, t1, t2;
    if (t < 14) {
        const float* p = conv + t * 3;
        t0 = p[0]; t1 = p[1]; t2 = p[2];
    } else if (t < 18) { t0 = pool[0]; t1 = pool[1]; t2 = pool[2]; }
    else if (t < 20)   { t0 = pool[3]; t1 = pool[4]; t2 = pool[5]; }
    else               { t0 = pool[6]; t1 = pool[7]; t2 = pool[8]; }

    float sg = 0.5f * (t1 + t2), dl = 0.5f * (t2 - t1);
    float cs = cosf(sg), ss = sinf(sg);
    float cd = cosf(dl), sd = sinf(dl);
    float cp = cosf(t0), sp = sinf(t0);
    u64* o = g_coef + t * 6;
    o[0] = pk2(cs, cs); o[1] = pk2(ss, ss);
    o[2] = pk2(cp * cd, cp * cd); o[3] = pk2(sp * cd, sp * cd);
    o[4] = pk2(cp * sd, cp * sd); o[5] = pk2(sp * sd, sp * sd);
}

// ---------------- fused-block kernels (packed state R[4], I[4]) ----------------

// both control & target in register bits (CB,TB >= 5); PB != CB-5, TB-5
template<int CB, int TB, int PB>
__device__ __forceinline__ void blk_reg(u64 (&R)[4], u64 (&I)[4], const u64* cf) {
    constexpr int cb = CB - 5, tb = TB - 5;
    u64 cs = cf[0], ss = cf[1], ar = cf[2], ai = cf[3], br = cf[4], bi = cf[5];
    u64 nss = neg2(ss), nai = neg2(ai), nbr = neg2(br), nbi = neg2(bi);
    {   // control = 0: real rotation
        constexpr int p0 = pidx(PB, 0), p1 = pidx(PB, 1 << tb);
        u64 x0r = R[p0], x1r = R[p1], x0i = I[p0], x1i = I[p1];
        R[p0] = fma2(nss, x1r, mul2(cs, x0r));
        I[p0] = fma2(nss, x1i, mul2(cs, x0i));
        R[p1] = fma2(cs, x1r, mul2(ss, x0r));
        I[p1] = fma2(cs, x1i, mul2(ss, x0i));
    }
    {   // control = 1: u0 = -b*x0 + a*x1 ; u1 = a*x0 + b*x1 (complex)
        constexpr int p0 = pidx(PB, 1 << cb), p1 = pidx(PB, (1 << cb) | (1 << tb));
        u64 x0r = R[p0], x0i = I[p0], x1r = R[p1], x1i = I[p1];
        R[p0] = fma2(nai, x1i, fma2(ar, x1r, fma2(bi,  x0i, mul2(nbr, x0r))));
        I[p0] = fma2(ai,  x1r, fma2(ar, x1i, fma2(nbi, x0r, mul2(nbr, x0i))));
        R[p1] = fma2(nbi, x1i, fma2(br, x1r, fma2(nai, x0i, mul2(ar, x0r))));
        I[p1] = fma2(bi,  x1r, fma2(br, x1i, fma2(ai,  x0r, mul2(ar, x0i))));
    }
}

// control in register bit (CB>=5), target in lane bit TB (<5); PB != CB-5
template<int CB, int TB, int PB>
__device__ __forceinline__ void blk_xreg(u64 (&R)[4], u64 (&I)[4], const u64* cf,
                                         unsigned lane) {
    constexpr int cb = CB - 5, m = 1 << TB;
    u64 cs = cf[0], ss = cf[1], ar = cf[2], ai = cf[3], br = cf[4], bi = cf[5];
    u64 nai = neg2(ai);
    const bool side = (lane >> TB) & 1;
    u64 Bs   = side ? ss : neg2(ss);
    u64 Car  = side ? br : neg2(br);
    u64 Cain = side ? neg2(bi) : bi;   // coef of xi in re'
    u64 Caii = neg2(Cain);             // coef of xr in im'
#pragma unroll
    for (int p = 0; p < 4; p++) {
        float xlo, xhi, ylo, yhi;
        upk2(R[p], xlo, xhi); upk2(I[p], ylo, yhi);
        u64 Pr = pk2(__shfl_xor_sync(FULL, xlo, m), __shfl_xor_sync(FULL, xhi, m));
        u64 Pi = pk2(__shfl_xor_sync(FULL, ylo, m), __shfl_xor_sync(FULL, yhi, m));
        const int base = expnd(PB, p);
        if (((base >> cb) & 1) == 0) {
            R[p] = fma2(Bs, Pr, mul2(cs, R[p]));
            I[p] = fma2(Bs, Pi, mul2(cs, I[p]));
        } else {
            u64 xr = R[p], xi = I[p];
            R[p] = fma2(nai, Pi, fma2(ar, Pr, fma2(Cain, xi, mul2(Car, xr))));
            I[p] = fma2(ai,  Pr, fma2(ar, Pi, fma2(Caii, xr, mul2(Car, xi))));
        }
    }
}

// control in lane bit (CB<5), target in lane bit TB; any PB
template<int CB, int TB, int PB>
__device__ __forceinline__ void blk_xlane(u64 (&R)[4], u64 (&I)[4], const u64* cf,
                                          unsigned lane) {
    constexpr int m = 1 << TB;
    u64 cs = cf[0], ss = cf[1], ar = cf[2], ai = cf[3], br = cf[4], bi = cf[5];
    const bool side = (lane >> TB) & 1;
    const bool c    = (lane >> CB) & 1;
    const u64 Z = 0;
    u64 pAr = c ? (side ? br : neg2(br)) : cs;
    u64 pAi = c ? (side ? bi : neg2(bi)) : Z;
    u64 pnAi = neg2(pAi);
    u64 pBr = c ? ar : (side ? ss : neg2(ss));
    u64 pBi = c ? ai : Z;
    u64 pnBi = neg2(pBi);
#pragma unroll
    for (int p = 0; p < 4; p++) {
        float xlo, xhi, ylo, yhi;
        upk2(R[p], xlo, xhi); upk2(I[p], ylo, yhi);
        u64 Pr = pk2(__shfl_xor_sync(FULL, xlo, m), __shfl_xor_sync(FULL, xhi, m));
        u64 Pi = pk2(__shfl_xor_sync(FULL, ylo, m), __shfl_xor_sync(FULL, yhi, m));
        u64 xr = R[p], xi = I[p];
        R[p] = fma2(pnBi, Pi, fma2(pBr, Pr, fma2(pnAi, xi, mul2(pAr, xr))));
        I[p] = fma2(pBi,  Pr, fma2(pBr, Pi, fma2(pAi,  xr, mul2(pAr, xi))));
    }
}

template<int A, int B>
__device__ __forceinline__ void repack1(u64 (&X)[4]) {
    float v[8];
#pragma unroll
    for (int p = 0; p < 4; p++) {
        const int b = expnd(A, p);
        upk2(X[p], v[b], v[b | (1 << A)]);
    }
#pragma unroll
    for (int p = 0; p < 4; p++) {
        const int b = expnd(B, p);
        X[p] = pk2(v[b], v[b | (1 << B)]);
    }
}
template<int A, int B>
__device__ __forceinline__ void repack(u64 (&R)[4], u64 (&I)[4]) {
    repack1<A, B>(R); repack1<A, B>(I);
}

// ---------------- main kernel ----------------
__global__ void __launch_bounds__(256)
qsim_kernel(const float* __restrict__ x, float* __restrict__ out, int nb) {
    __shared__ u64 scf[21 * 6];
    for (int t = threadIdx.x; t < 21 * 6; t += blockDim.x) scf[t] = g_coef[t];
    __syncthreads();

    const int warp = threadIdx.x >> 5;
    const unsigned lane = threadIdx.x & 31;
    const int b = blockIdx.x * (blockDim.x >> 5) + warp;
    if (b >= nb) return;

    // ---- initial product state: amp[i] = prod_q (bit(7-q,i) ? sin(x_q/2) : cos(x_q/2))
    float myx = x[b * 8 + (lane & 7)];
    float sh_, ch_;
    sincosf(0.5f * myx, &sh_, &ch_);
    float cw[8], sw[8];
#pragma unroll
    for (int w = 0; w < 8; w++) {
        cw[w] = __shfl_sync(FULL, ch_, w);
        sw[w] = __shfl_sync(FULL, sh_, w);
    }
    float pref = 1.f;
#pragma unroll
    for (int k = 0; k < 5; k++)
        pref *= ((lane >> k) & 1) ? sw[7 - k] : cw[7 - k];
    float q01[4];
    q01[0] = cw[0] * cw[1]; q01[1] = cw[0] * sw[1];
    q01[2] = sw[0] * cw[1]; q01[3] = sw[0] * sw[1];
    float re[8];
#pragma unroll
    for (int r = 0; r < 8; r++)
        re[r] = q01[r >> 1] * ((r & 1) ? sw[2] : cw[2]) * pref;

    u64 R[4], I[4];
#pragma unroll
    for (int p = 0; p < 4; p++) {            // pack with PB=0: pairs (2p, 2p+1)
        R[p] = pk2(re[2 * p], re[2 * p + 1]);
        I[p] = 0ull;
    }

    // ---- 21 fused blocks; conv i: (CB,TB) = (7-i, 6-i)
    blk_reg <7, 6, 0>(R, I, scf + 0 * 6);
    repack<0, 2>(R, I);
    blk_reg <6, 5, 2>(R, I, scf + 1 * 6);
    blk_xreg<5, 4, 2>(R, I, scf + 2 * 6, lane);
    blk_xlane<4, 3, 2>(R, I, scf + 3 * 6, lane);
    blk_xlane<3, 2, 2>(R, I, scf + 4 * 6, lane);
    blk_xlane<2, 1, 2>(R, I, scf + 5 * 6, lane);
    blk_xlane<1, 0, 2>(R, I, scf + 6 * 6, lane);

    repack<2, 0>(R, I);
    blk_reg <7, 6, 0>(R, I, scf + 7 * 6);
    repack<0, 2>(R, I);
    blk_reg <6, 5, 2>(R, I, scf + 8 * 6);
    blk_xreg<5, 4, 2>(R, I, scf + 9 * 6, lane);
    blk_xlane<4, 3, 2>(R, I, scf + 10 * 6, lane);
    blk_xlane<3, 2, 2>(R, I, scf + 11 * 6, lane);
    blk_xlane<2, 1, 2>(R, I, scf + 12 * 6, lane);
    blk_xlane<1, 0, 2>(R, I, scf + 13 * 6, lane);

    // pool0: wires (0,4),(1,5),(2,6),(3,7) -> bits (7,3),(6,2),(5,1),(4,0)
    repack<2, 0>(R, I);
    blk_xreg<7, 3, 0>(R, I, scf + 14 * 6, lane);
    blk_xreg<6, 2, 0>(R, I, scf + 15 * 6, lane);
    repack<0, 1>(R, I);
    blk_xreg<5, 1, 1>(R, I, scf + 16 * 6, lane);
    blk_xlane<4, 0, 1>(R, I, scf + 17 * 6, lane);
    // pool1: (0,2),(1,3) -> (7,5),(6,4)
    blk_reg <7, 5, 1>(R, I, scf + 18 * 6);
    repack<1, 0>(R, I);
    blk_xreg<6, 4, 0>(R, I, scf + 19 * 6, lane);
    // pool2: (0,1) -> (7,6)
    blk_reg <7, 6, 0>(R, I, scf + 20 * 6);

    // ---- readout: <Z_q> = sum_i |amp_i|^2 * (-1)^{bit(7-q,i)}
    float rr[8], ii[8];
#pragma unroll
    for (int p = 0; p < 4; p++) {            // PB=0 unpack
        upk2(R[p], rr[2 * p], rr[2 * p + 1]);
        upk2(I[p], ii[2 * p], ii[2 * p + 1]);
    }
    float pz[8];
#pragma unroll
    for (int r = 0; r < 8; r++) pz[r] = rr[r] * rr[r] + ii[r] * ii[r];

    float a0 = pz[0] + pz[1], a1 = pz[2] + pz[3], a2 = pz[4] + pz[5], a3 = pz[6] + pz[7];
    float b01 = a0 + a1, b23 = a2 + a3;
    float S = b01 + b23;
    float v[8];
    v[0] = b01 - b23;
    v[1] = (a0 - a1) + (a2 - a3);
    v[2] = (pz[0] - pz[1]) + (pz[2] - pz[3]) + (pz[4] - pz[5]) + (pz[6] - pz[7]);
    v[3] = S; v[4] = S; v[5] = S; v[6] = S; v[7] = S;

#pragma unroll
    for (int k = 0; k < 5; k++) {
        const int m = 1 << k;
        const int qs = 7 - k;
        const bool hi = (lane >> k) & 1;
#pragma unroll
        for (int j = 0; j < 8; j++) {
            float t = __shfl_xor_sync(FULL, v[j], m);
            if (j == qs) v[j] = hi ? (t - v[j]) : (v[j] - t);
            else         v[j] = v[j] + t;
        }
    }

    if (lane == 0) {
        float4* o = (float4*)(out + (size_t)b * 8);
        o[0] = make_float4(v[0], v[1], v[2], v[3]);
        o[1] = make_float4(v[4], v[5], v[6], v[7]);
    }
}

extern "C" void kernel_launch(void* const* d_in, const int* in_sizes, int n_in,
                              void* d_out, int out_size) {
    const float* x    = (const float*)d_in[0];
    const float* conv = (const float*)d_in[1];
    const float* pool = (const float*)d_in[2];
    float* out = (float*)d_out;

    int nb = in_sizes[0] / 8;   // 65536 batch elements

    setup_coef<<<1, 32>>>(conv, pool);

    const int WARPS_PER_BLOCK = 8;
    int blocks = (nb + WARPS_PER_BLOCK - 1) / WARPS_PER_BLOCK;
    qsim_kernel<<<blocks, WARPS_PER_BLOCK * 32>>>(x, out, nb);
}

// round 3
// speedup vs baseline: 1.1574x; 1.1574x over previous
#include <cuda_runtime.h>
#include <math.h>

#define FULL 0xffffffffu
typedef unsigned long long u64;

// ---------------- f32x2 helpers (lo = batch A, hi = batch B) ----------------
__device__ __forceinline__ u64 pk2(float lo, float hi) {
    u64 r; asm("mov.b64 %0,{%1,%2};" : "=l"(r) : "f"(lo), "f"(hi)); return r;
}
__device__ __forceinline__ void upk2(u64 v, float& lo, float& hi) {
    asm("mov.b64 {%0,%1},%2;" : "=f"(lo), "=f"(hi) : "l"(v));
}
__device__ __forceinline__ u64 fma2(u64 a, u64 b, u64 c) {
    u64 d; asm("fma.rn.f32x2 %0,%1,%2,%3;" : "=l"(d) : "l"(a), "l"(b), "l"(c)); return d;
}
__device__ __forceinline__ u64 mul2(u64 a, u64 b) {
    u64 d; asm("mul.rn.f32x2 %0,%1,%2;" : "=l"(d) : "l"(a), "l"(b)); return d;
}
__device__ __forceinline__ u64 add2(u64 a, u64 b) {
    u64 d; asm("add.rn.f32x2 %0,%1,%2;" : "=l"(d) : "l"(a), "l"(b)); return d;
}
__device__ __forceinline__ u64 neg2(u64 a) { return a ^ 0x8000000080000000ull; }
// a - b in one instruction: fma(b, -1, a)
#define M1C 0xBF800000BF800000ull
__device__ __forceinline__ u64 sub2(u64 a, u64 b) { return fma2(b, M1C, a); }

__device__ __forceinline__ u64 shfl_xor64(u64 v, int m) {
    float lo, hi; upk2(v, lo, hi);
    lo = __shfl_xor_sync(FULL, lo, m);
    hi = __shfl_xor_sync(FULL, hi, m);
    return pk2(lo, hi);
}

// ---------------- coefficients ----------------
// Fused block (RZ(c) -> RY(t) -> CNOT -> RY(t)) is block-diagonal over control:
//  c=0: real rotation by sigma=(t1+t2)/2 (global phase dropped)
//  c=1: e^{i t0} * [[-sin d, cos d],[cos d, sin d]], d=(t2-t1)/2
//       -> a = e^{i t0} cos d, b = e^{i t0} sin d
// Stored duplicated as f32x2: [cs, ss, ar, ai, br, bi]
__device__ u64 g_coef[21 * 6];

__global__ void setup_coef(const float* __restrict__ conv,
                           const float* __restrict__ pool) {
    int t = threadIdx.x;
    if (t >= 21) return;
    float t0, t1, t2;
    if (t < 14) {
        const float* p = conv + t * 3;
        t0 = p[0]; t1 = p[1]; t2 = p[2];
    } else if (t < 18) { t0 = pool[0]; t1 = pool[1]; t2 = pool[2]; }
    else if (t < 20)   { t0 = pool[3]; t1 = pool[4]; t2 = pool[5]; }
    else               { t0 = pool[6]; t1 = pool[7]; t2 = pool[8]; }

    float sg = 0.5f * (t1 + t2), dl = 0.5f * (t2 - t1);
    float cs = cosf(sg), ss = sinf(sg);
    float cd = cosf(dl), sd = sinf(dl);
    float cp = cosf(t0), sp = sinf(t0);
    u64* o = g_coef + t * 6;
    o[0] = pk2(cs, cs); o[1] = pk2(ss, ss);
    o[2] = pk2(cp * cd, cp * cd); o[3] = pk2(sp * cd, sp * cd);
    o[4] = pk2(cp * sd, cp * sd); o[5] = pk2(sp * sd, sp * sd);
}

// ---------------- fused-block kernels ----------------
// State: 8 register slots (index bits {7,6,5}: slot bit2=idx7, bit1=idx6, bit0=idx5),
// lane bits k=0..4 = index bits k. Each u64 carries (batch A, batch B).

// control & target both register bits (CB,TB >= 5)
template<int CB, int TB>
__device__ __forceinline__ void blk_reg(u64 (&R)[8], u64 (&I)[8], const u64* cf) {
    constexpr int cb = CB - 5, tm = 1 << (TB - 5);
    u64 cs = cf[0], ss = cf[1], ar = cf[2], ai = cf[3], br = cf[4], bi = cf[5];
    u64 nss = neg2(ss), nai = neg2(ai), nbr = neg2(br), nbi = neg2(bi);
#pragma unroll
    for (int r0 = 0; r0 < 8; r0++) {
        if (r0 & tm) continue;
        const int r1 = r0 | tm;
        u64 x0r = R[r0], x0i = I[r0], x1r = R[r1], x1i = I[r1];
        if (((r0 >> cb) & 1) == 0) {
            R[r0] = fma2(nss, x1r, mul2(cs, x0r));
            I[r0] = fma2(nss, x1i, mul2(cs, x0i));
            R[r1] = fma2(cs, x1r, mul2(ss, x0r));
            I[r1] = fma2(cs, x1i, mul2(ss, x0i));
        } else {
            R[r0] = fma2(nai, x1i, fma2(ar, x1r, fma2(bi,  x0i, mul2(nbr, x0r))));
            I[r0] = fma2(ai,  x1r, fma2(ar, x1i, fma2(nbi, x0r, mul2(nbr, x0i))));
            R[r1] = fma2(nbi, x1i, fma2(br, x1r, fma2(nai, x0i, mul2(ar, x0r))));
            I[r1] = fma2(bi,  x1r, fma2(br, x1i, fma2(ai,  x0r, mul2(ar, x0i))));
        }
    }
}

// control in register bit (CB>=5), target in lane bit TB (<5)
template<int CB, int TB>
__device__ __forceinline__ void blk_xreg(u64 (&R)[8], u64 (&I)[8], const u64* cf,
                                         unsigned lane) {
    constexpr int cb = CB - 5, m = 1 << TB;
    u64 cs = cf[0], ss = cf[1], ar = cf[2], ai = cf[3], br = cf[4], bi = cf[5];
    u64 nai = neg2(ai);
    const bool side = (lane >> TB) & 1;   // 0: this lane holds t0; 1: holds t1
    u64 Bs = side ? ss : neg2(ss);
    u64 Ar = side ? br : neg2(br);
    u64 Ai = side ? bi : neg2(bi);
    u64 nAi = neg2(Ai);
#pragma unroll
    for (int r = 0; r < 8; r++) {
        u64 Pr = shfl_xor64(R[r], m);
        u64 Pi = shfl_xor64(I[r], m);
        if (((r >> cb) & 1) == 0) {
            R[r] = fma2(Bs, Pr, mul2(cs, R[r]));
            I[r] = fma2(Bs, Pi, mul2(cs, I[r]));
        } else {
            u64 xr = R[r], xi = I[r];
            R[r] = fma2(nai, Pi, fma2(ar, Pr, fma2(nAi, xi, mul2(Ar, xr))));
            I[r] = fma2(ai,  Pr, fma2(ar, Pi, fma2(Ai,  xr, mul2(Ar, xi))));
        }
    }
}

// control and target both lane bits (CB,TB < 5)
template<int CB, int TB>
__device__ __forceinline__ void blk_xlane(u64 (&R)[8], u64 (&I)[8], const u64* cf,
                                          unsigned lane) {
    constexpr int m = 1 << TB;
    u64 cs = cf[0], ss = cf[1], ar = cf[2], ai = cf[3], br = cf[4], bi = cf[5];
    const bool side = (lane >> TB) & 1;
    const bool c    = (lane >> CB) & 1;
    const u64 Z = 0;
    u64 Ar = c ? (side ? br : neg2(br)) : cs;
    u64 Ai = c ? (side ? bi : neg2(bi)) : Z;
    u64 Br = c ? ar : (side ? ss : neg2(ss));
    u64 Bi = c ? ai : Z;
    u64 nAi = neg2(Ai), nBi = neg2(Bi);
#pragma unroll
    for (int r = 0; r < 8; r++) {
        u64 Pr = shfl_xor64(R[r], m);
        u64 Pi = shfl_xor64(I[r], m);
        u64 xr = R[r], xi = I[r];
        R[r] = fma2(nBi, Pi, fma2(Br, Pr, fma2(nAi, xi, mul2(Ar, xr))));
        I[r] = fma2(Bi,  Pr, fma2(Br, Pi, fma2(Ai,  xr, mul2(Ar, xi))));
    }
}

// ---------------- main kernel ----------------
__global__ void __launch_bounds__(256)
qsim_kernel(const float* __restrict__ x, float* __restrict__ out, int nb2) {
    __shared__ u64 scf[21 * 6];
    for (int t = threadIdx.x; t < 21 * 6; t += blockDim.x)
        scf[t] = g_coef[t];
    __syncthreads();

    const int warp = threadIdx.x >> 5;
    const unsigned lane = threadIdx.x & 31;
    const int w = blockIdx.x * (blockDim.x >> 5) + warp;
    if (w >= nb2) return;
    const int bA = 2 * w, bB = 2 * w + 1;

    // ---- initial product state for both batches
    // lanes 0-7 load batch A angles, lanes 8-15 batch B (16-31 duplicate A/B)
    const int myb = ((lane >> 3) & 1) ? bB : bA;
    float myx = x[myb * 8 + (lane & 7)];
    float sh_, ch_;
    sincosf(0.5f * myx, &sh_, &ch_);
    float cA[8], sA[8], cB[8], sB[8];
#pragma unroll
    for (int q = 0; q < 8; q++) {
        cA[q] = __shfl_sync(FULL, ch_, q);
        sA[q] = __shfl_sync(FULL, sh_, q);
        cB[q] = __shfl_sync(FULL, ch_, q + 8);
        sB[q] = __shfl_sync(FULL, sh_, q + 8);
    }
    // amp[i] = prod_q (bit(7-q,i) ? sin : cos); lane bit k = index bit k -> wire 7-k
    float prA = 1.f, prB = 1.f;
#pragma unroll
    for (int k = 0; k < 5; k++) {
        const bool hi = (lane >> k) & 1;
        prA *= hi ? sA[7 - k] : cA[7 - k];
        prB *= hi ? sB[7 - k] : cB[7 - k];
    }
    u64 R[8], I[8];
#pragma unroll
    for (int r = 0; r < 8; r++) {
        float fA = ((r & 4) ? sA[0] : cA[0]) * ((r & 2) ? sA[1] : cA[1]) *
                   ((r & 1) ? sA[2] : cA[2]) * prA;
        float fB = ((r & 4) ? sB[0] : cB[0]) * ((r & 2) ? sB[1] : cB[1]) *
                   ((r & 1) ? sB[2] : cB[2]) * prB;
        R[r] = pk2(fA, fB);
        I[r] = 0ull;
    }

    // ---- 21 fused blocks; conv i: (CB,TB) = (7-i, 6-i)
    blk_reg <7, 6>(R, I, scf + 0 * 6);
    blk_reg <6, 5>(R, I, scf + 1 * 6);
    blk_xreg<5, 4>(R, I, scf + 2 * 6, lane);
    blk_xlane<4, 3>(R, I, scf + 3 * 6, lane);
    blk_xlane<3, 2>(R, I, scf + 4 * 6, lane);
    blk_xlane<2, 1>(R, I, scf + 5 * 6, lane);
    blk_xlane<1, 0>(R, I, scf + 6 * 6, lane);

    blk_reg <7, 6>(R, I, scf + 7 * 6);
    blk_reg <6, 5>(R, I, scf + 8 * 6);
    blk_xreg<5, 4>(R, I, scf + 9 * 6, lane);
    blk_xlane<4, 3>(R, I, scf + 10 * 6, lane);
    blk_xlane<3, 2>(R, I, scf + 11 * 6, lane);
    blk_xlane<2, 1>(R, I, scf + 12 * 6, lane);
    blk_xlane<1, 0>(R, I, scf + 13 * 6, lane);

    // pool0: wires (0,4),(1,5),(2,6),(3,7) -> bits (7,3),(6,2),(5,1),(4,0)
    blk_xreg<7, 3>(R, I, scf + 14 * 6, lane);
    blk_xreg<6, 2>(R, I, scf + 15 * 6, lane);
    blk_xreg<5, 1>(R, I, scf + 16 * 6, lane);
    blk_xlane<4, 0>(R, I, scf + 17 * 6, lane);
    // pool1: (0,2),(1,3) -> (7,5),(6,4)
    blk_reg <7, 5>(R, I, scf + 18 * 6);
    blk_xreg<6, 4>(R, I, scf + 19 * 6, lane);
    // pool2: (0,1) -> (7,6)
    blk_reg <7, 6>(R, I, scf + 20 * 6);

    // ---- readout: <Z_q> = sum_i |amp_i|^2 * (-1)^{bit(7-q,i)}  (packed, both batches)
    u64 pz[8];
#pragma unroll
    for (int r = 0; r < 8; r++) pz[r] = fma2(R[r], R[r], mul2(I[r], I[r]));

    u64 a0 = add2(pz[0], pz[1]), a1 = add2(pz[2], pz[3]);
    u64 a2 = add2(pz[4], pz[5]), a3 = add2(pz[6], pz[7]);
    u64 b01 = add2(a0, a1), b23 = add2(a2, a3);
    u64 S = add2(b01, b23);
    u64 v[8];
    v[0] = sub2(b01, b23);                          // wire0 (slot bit 2 = idx bit 7)
    v[1] = add2(sub2(a0, a1), sub2(a2, a3));        // wire1 (slot bit 1)
    v[2] = add2(add2(sub2(pz[0], pz[1]), sub2(pz[2], pz[3])),
                add2(sub2(pz[4], pz[5]), sub2(pz[6], pz[7])));  // wire2 (slot bit 0)
    v[3] = S; v[4] = S; v[5] = S; v[6] = S; v[7] = S;

#pragma unroll
    for (int k = 0; k < 5; k++) {
        const int m = 1 << k;
        const int qs = 7 - k;          // output whose sign flips with lane bit k
        const bool hi = (lane >> k) & 1;
#pragma unroll
        for (int j = 0; j < 8; j++) {
            u64 t = shfl_xor64(v[j], m);
            if (j == qs) v[j] = hi ? sub2(t, v[j]) : sub2(v[j], t);
            else         v[j] = add2(v[j], t);
        }
    }

    if (lane == 0) {
        float lo[8], hi[8];
#pragma unroll
        for (int j = 0; j < 8; j++) upk2(v[j], lo[j], hi[j]);
        float4* oA = (float4*)(out + (size_t)bA * 8);
        oA[0] = make_float4(lo[0], lo[1], lo[2], lo[3]);
        oA[1] = make_float4(lo[4], lo[5], lo[6], lo[7]);
        float4* oB = (float4*)(out + (size_t)bB * 8);
        oB[0] = make_float4(hi[0], hi[1], hi[2], hi[3]);
        oB[1] = make_float4(hi[4], hi[5], hi[6], hi[7]);
    }
}

extern "C" void kernel_launch(void* const* d_in, const int* in_sizes, int n_in,
                              void* d_out, int out_size) {
    const float* x    = (const float*)d_in[0];
    const float* conv = (const float*)d_in[1];
    const float* pool = (const float*)d_in[2];
    float* out = (float*)d_out;

    int nb = in_sizes[0] / 8;    // 65536 batch elements
    int nb2 = nb / 2;            // two batches per warp

    setup_coef<<<1, 32>>>(conv, pool);

    const int WARPS_PER_BLOCK = 8;
    int blocks = (nb2 + WARPS_PER_BLOCK - 1) / WARPS_PER_BLOCK;
    qsim_kernel<<<blocks, WARPS_PER_BLOCK * 32>>>(x, out, nb2);
}

// round 6
// speedup vs baseline: 1.5516x; 1.3407x over previous
#include <cuda_runtime.h>
#include <cuda_fp16.h>
#include <cstdint>
#include <math.h>

#define FULL 0xffffffffu

// ===================== device globals =====================
__device__ float  g_coef[21 * 6];          // per fused block: cs, ss, ar, ai, br, bi
__device__ __half g_Ure[256 * 256];        // U_re[i][k], K-major
__device__ __half g_Uim[256 * 256];        // U_im[i][k], K-major

// ===================== coefficient setup =====================
__global__ void setup_coef(const float* __restrict__ conv,
                           const float* __restrict__ pool) {
    int t = threadIdx.x;
    if (t >= 21) return;
    float t0, t1, t2;
    if (t < 14)        { const float* p = conv + t * 3; t0 = p[0]; t1 = p[1]; t2 = p[2]; }
    else if (t < 18)   { t0 = pool[0]; t1 = pool[1]; t2 = pool[2]; }
    else if (t < 20)   { t0 = pool[3]; t1 = pool[4]; t2 = pool[5]; }
    else               { t0 = pool[6]; t1 = pool[7]; t2 = pool[8]; }
    float sg = 0.5f * (t1 + t2), dl = 0.5f * (t2 - t1);
    float cs = cosf(sg), ss = sinf(sg);
    float cd = cosf(dl), sd = sinf(dl);
    float cp = cosf(t0), sp = sinf(t0);
    float* o = g_coef + t * 6;
    o[0] = cs; o[1] = ss;
    o[2] = cp * cd; o[3] = sp * cd;
    o[4] = cp * sd; o[5] = sp * sd;
}

// ===================== scalar fused-block sim (validated in R1) =====================
template<int CB, int TB>
__device__ __forceinline__ void apply_block(float (&re)[8], float (&im)[8],
                                            const float* cf, unsigned lane) {
    float cs = cf[0], ss = cf[1];
    float ar = cf[2], ai = cf[3], br = cf[4], bi = cf[5];
    if constexpr (TB >= 5) {
        static_assert(CB >= 5, "in-lane target gates have in-register control");
        constexpr int tm = 1 << (TB - 5);
#pragma unroll
        for (int r0 = 0; r0 < 8; r0++) {
            if (r0 & tm) continue;
            const int r1 = r0 | tm;
            float x0r = re[r0], x0i = im[r0], x1r = re[r1], x1i = im[r1];
            if (((r0 >> (CB - 5)) & 1) == 0) {
                re[r0] = cs * x0r - ss * x1r;  im[r0] = cs * x0i - ss * x1i;
                re[r1] = ss * x0r + cs * x1r;  im[r1] = ss * x0i + cs * x1i;
            } else {
                re[r0] = -br * x0r + bi * x0i + ar * x1r - ai * x1i;
                im[r0] = -br * x0i - bi * x0r + ar * x1i + ai * x1r;
                re[r1] =  ar * x0r - ai * x0i + br * x1r - bi * x1i;
                im[r1] =  ar * x0i + ai * x0r + br * x1i + bi * x1r;
            }
        }
    } else {
        const bool side = (lane >> TB) & 1;
        if constexpr (CB >= 5) {
            float Bs = side ? ss : -ss;
            float Ar = side ? br : -br;
            float Ai = side ? bi : -bi;
#pragma unroll
            for (int r = 0; r < 8; r++) {
                float pr = __shfl_xor_sync(FULL, re[r], 1 << TB);
                float pi = __shfl_xor_sync(FULL, im[r], 1 << TB);
                if (((r >> (CB - 5)) & 1) == 0) {
                    re[r] = cs * re[r] + Bs * pr;
                    im[r] = cs * im[r] + Bs * pi;
                } else {
                    float xr = re[r], xi = im[r];
                    re[r] = Ar * xr - Ai * xi + ar * pr - ai * pi;
                    im[r] = Ar * xi + Ai * xr + ar * pi + ai * pr;
                }
            }
        } else {
            const bool c = (lane >> CB) & 1;
            float Ar, Ai, Br, Bi;
            if (c) { Ar = side ? br : -br; Ai = side ? bi : -bi; Br = ar; Bi = ai; }
            else   { Ar = cs; Ai = 0.f;    Br = side ? ss : -ss; Bi = 0.f; }
#pragma unroll
            for (int r = 0; r < 8; r++) {
                float pr = __shfl_xor_sync(FULL, re[r], 1 << TB);
                float pi = __shfl_xor_sync(FULL, im[r], 1 << TB);
                float xr = re[r], xi = im[r];
                re[r] = Ar * xr - Ai * xi + Br * pr - Bi * pi;
                im[r] = Ar * xi + Ai * xr + Br * pi + Bi * pr;
            }
        }
    }
}

__device__ __forceinline__ void run_circuit(float (&re)[8], float (&im)[8], unsigned lane) {
    apply_block<7, 6>(re, im, g_coef + 0 * 6, lane);
    apply_block<6, 5>(re, im, g_coef + 1 * 6, lane);
    apply_block<5, 4>(re, im, g_coef + 2 * 6, lane);
    apply_block<4, 3>(re, im, g_coef + 3 * 6, lane);
    apply_block<3, 2>(re, im, g_coef + 4 * 6, lane);
    apply_block<2, 1>(re, im, g_coef + 5 * 6, lane);
    apply_block<1, 0>(re, im, g_coef + 6 * 6, lane);
    apply_block<7, 6>(re, im, g_coef + 7 * 6, lane);
    apply_block<6, 5>(re, im, g_coef + 8 * 6, lane);
    apply_block<5, 4>(re, im, g_coef + 9 * 6, lane);
    apply_block<4, 3>(re, im, g_coef + 10 * 6, lane);
    apply_block<3, 2>(re, im, g_coef + 11 * 6, lane);
    apply_block<2, 1>(re, im, g_coef + 12 * 6, lane);
    apply_block<1, 0>(re, im, g_coef + 13 * 6, lane);
    apply_block<7, 3>(re, im, g_coef + 14 * 6, lane);
    apply_block<6, 2>(re, im, g_coef + 15 * 6, lane);
    apply_block<5, 1>(re, im, g_coef + 16 * 6, lane);
    apply_block<4, 0>(re, im, g_coef + 17 * 6, lane);
    apply_block<7, 5>(re, im, g_coef + 18 * 6, lane);
    apply_block<6, 4>(re, im, g_coef + 19 * 6, lane);
    apply_block<7, 6>(re, im, g_coef + 20 * 6, lane);
}

// build U columns: warp w simulates basis state e_k, k = global warp id
__global__ void build_u() {
    const int wid = threadIdx.x >> 5;
    const unsigned lane = threadIdx.x & 31;
    const int k = blockIdx.x * (blockDim.x >> 5) + wid;
    float re[8], im[8];
#pragma unroll
    for (int r = 0; r < 8; r++) {
        re[r] = (r == (k >> 5) && lane == (unsigned)(k & 31)) ? 1.f : 0.f;
        im[r] = 0.f;
    }
    run_circuit(re, im, lane);
#pragma unroll
    for (int r = 0; r < 8; r++) {
        int i = (r << 5) | lane;
        g_Ure[i * 256 + k] = __float2half(re[r]);
        g_Uim[i * 256 + k] = __float2half(im[r]);
    }
}

// ===================== HMMA helpers =====================
__device__ __forceinline__ uint32_t smem_u32(const void* p) {
    uint32_t a;
    asm("{ .reg .u64 t; cvta.to.shared.u64 t, %1; cvt.u32.u64 %0, t; }" : "=r"(a) : "l"(p));
    return a;
}

__device__ __forceinline__ void ldsm_x4(uint32_t& r0, uint32_t& r1,
                                        uint32_t& r2, uint32_t& r3, uint32_t addr) {
    asm volatile("ldmatrix.sync.aligned.m8n8.x4.shared.b16 {%0,%1,%2,%3}, [%4];"
                 : "=r"(r0), "=r"(r1), "=r"(r2), "=r"(r3) : "r"(addr));
}

__device__ __forceinline__ void mma16816(float& c0, float& c1, float& c2, float& c3,
                                         uint32_t a0, uint32_t a1, uint32_t a2, uint32_t a3,
                                         uint32_t b0, uint32_t b1) {
    asm volatile("mma.sync.aligned.m16n8k16.row.col.f32.f16.f16.f32 "
                 "{%0,%1,%2,%3}, {%4,%5,%6,%7}, {%8,%9}, {%0,%1,%2,%3};"
                 : "+f"(c0), "+f"(c1), "+f"(c2), "+f"(c3)
                 : "r"(a0), "r"(a1), "r"(a2), "r"(a3), "r"(b0), "r"(b1));
}

// ===================== main GEMM kernel =====================
// B chunk in smem: 128 rows (64 Ure + 64 Uim) x 264 halfs (256 data + 8 pad)
static constexpr int BROW = 264;                       // halfs per smem row
static constexpr int SMEM_TOTAL = 128 * BROW * 2;      // 67584 bytes

__global__ void __launch_bounds__(256, 2)
qgemm(const float* __restrict__ x, float* __restrict__ out) {
    extern __shared__ __half smB[];
    const uint32_t smb = smem_u32(smB);
    const int tid  = threadIdx.x;
    const int wid  = tid >> 5;
    const int lane = tid & 31;
    const int quad = lane & 3;       // t%4
    const int qrow = lane >> 2;      // t/4

    // ---- A fragment in registers: rows rlo = base + qrow, rhi = rlo + 8
    const int base = (blockIdx.x * 8 + wid) * 16;
    uint32_t A2[2][16][2];           // [row sel][ktile][k lo/hi pair] as half2
    {
#pragma unroll
        for (int rs = 0; rs < 2; rs++) {
            const int row = base + qrow + rs * 8;
            const float4* xp = (const float4*)(x + (size_t)row * 8);
            float4 x0 = xp[0], x1 = xp[1];
            float xv[8] = {x0.x, x0.y, x0.z, x0.w, x1.x, x1.y, x1.z, x1.w};
            float c_[8], s_[8];
#pragma unroll
            for (int q = 0; q < 8; q++) sincosf(0.5f * xv[q], &s_[q], &c_[q]);
            // hi16[h]: h bit3=qubit0 ... bit0=qubit3 (k bits 7..4)
            float hi16[16];
#pragma unroll
            for (int h = 0; h < 16; h++)
                hi16[h] = ((h & 8) ? s_[0] : c_[0]) * ((h & 4) ? s_[1] : c_[1]) *
                          ((h & 2) ? s_[2] : c_[2]) * ((h & 1) ? s_[3] : c_[3]);
            // lo values at l = b3*8 + quad*2 + b0  (l bit3=qubit4, bits2..1=quad, bit0=qubit7)
            float q5 = (quad & 2) ? s_[5] : c_[5];
            float q6 = (quad & 1) ? s_[6] : c_[6];
            float m56 = q5 * q6;
            float l00 = c_[4] * m56 * c_[7], l01 = c_[4] * m56 * s_[7];
            float l10 = s_[4] * m56 * c_[7], l11 = s_[4] * m56 * s_[7];
#pragma unroll
            for (int kk = 0; kk < 16; kk++) {
                float h = hi16[kk];
                __half2 plo = __floats2half2_rn(h * l00, h * l01);
                __half2 phi = __floats2half2_rn(h * l10, h * l11);
                A2[rs][kk][0] = *(uint32_t*)&plo;
                A2[rs][kk][1] = *(uint32_t*)&phi;
            }
        }
    }

    // ---- per-thread accumulators (per row sel): z7,z4,z3,z2 signed sums; S total; z1,z0
    float z7a[2] = {0, 0}, z4a[2] = {0, 0}, z3a[2] = {0, 0}, z2a[2] = {0, 0};
    float Sa[2] = {0, 0}, z1a[2] = {0, 0}, z0a[2] = {0, 0};

    // ldmatrix address base for this lane: group 0/1 = Ure k-lo/k-hi, 2/3 = Uim
    const int lgrp = lane >> 3, lrow = lane & 7;
    const uint32_t lbase = smb +
        (uint32_t)((((lgrp & 2) ? 64 : 0) + lrow) * BROW + (lgrp & 1) * 8) * 2;

    for (int it = 0; it < 4; it++) {
        const int n0 = it * 64;
        // ---- load B chunk: smem rows 0-63 = Ure[n0..], 64-127 = Uim[n0..]
#pragma unroll
        for (int j = 0; j < 16; j++) {
            int c = j * 256 + tid;            // 16B chunk id, 4096 total
            int row = c >> 5, kc = (c & 31) * 8;
            const __half* src = (row < 64) ? (g_Ure + (size_t)(n0 + row) * 256 + kc)
                                           : (g_Uim + (size_t)(n0 + row - 64) * 256 + kc);
            *(uint4*)(smB + row * BROW + kc) = *(const uint4*)src;
        }
        __syncthreads();

        float Sc[2] = {0, 0};
#pragma unroll
        for (int nt = 0; nt < 8; nt++) {
            float cre[4] = {0, 0, 0, 0}, cim[4] = {0, 0, 0, 0};
#pragma unroll
            for (int kk = 0; kk < 16; kk++) {
                uint32_t bre0, bre1, bim0, bim1;
                ldsm_x4(bre0, bre1, bim0, bim1,
                        lbase + (uint32_t)(nt * 8 * BROW + kk * 16) * 2);
                mma16816(cre[0], cre[1], cre[2], cre[3],
                         A2[0][kk][0], A2[1][kk][0], A2[0][kk][1], A2[1][kk][1],
                         bre0, bre1);
                mma16816(cim[0], cim[1], cim[2], cim[3],
                         A2[0][kk][0], A2[1][kk][0], A2[0][kk][1], A2[1][kk][1],
                         bim0, bim1);
            }
            // p = re^2 + im^2 ; cols: c0 = it*64 + nt*8 + quad*2 (+1)
#pragma unroll
            for (int rs = 0; rs < 2; rs++) {
                float p0 = cre[2 * rs] * cre[2 * rs] + cim[2 * rs] * cim[2 * rs];
                float p1 = cre[2 * rs + 1] * cre[2 * rs + 1] + cim[2 * rs + 1] * cim[2 * rs + 1];
                float d = p0 - p1, s = p0 + p1;
                z7a[rs] += d;
                Sc[rs] += s;
                z4a[rs] += (nt & 1) ? -s : s;
                z3a[rs] += (nt & 2) ? -s : s;
                z2a[rs] += (nt & 4) ? -s : s;
            }
        }
#pragma unroll
        for (int rs = 0; rs < 2; rs++) {
            Sa[rs] += Sc[rs];
            z1a[rs] += (it & 1) ? -Sc[rs] : Sc[rs];
            z0a[rs] += (it & 2) ? -Sc[rs] : Sc[rs];
        }
        __syncthreads();
    }

    // ---- finalize: z6/z5 from lane-constant signs on S; butterfly over quad lanes
#pragma unroll
    for (int rs = 0; rs < 2; rs++) {
        float z[8];
        z[0] = z0a[rs]; z[1] = z1a[rs]; z[2] = z2a[rs]; z[3] = z3a[rs];
        z[4] = z4a[rs];
        z[5] = ((quad >> 1) & 1) ? -Sa[rs] : Sa[rs];
        z[6] = (quad & 1) ? -Sa[rs] : Sa[rs];
        z[7] = z7a[rs];
#pragma unroll
        for (int q = 0; q < 8; q++) {
            z[q] += __shfl_xor_sync(FULL, z[q], 1);
            z[q] += __shfl_xor_sync(FULL, z[q], 2);
        }
        const int row = base + qrow + rs * 8;
        float2* o = (float2*)(out + (size_t)row * 8 + 2 * quad);
        *o = make_float2(z[2 * quad], z[2 * quad + 1]);
    }
}

// ===================== host launcher =====================
extern "C" void kernel_launch(void* const* d_in, const int* in_sizes, int n_in,
                              void* d_out, int out_size) {
    const float* x    = (const float*)d_in[0];
    const float* conv = (const float*)d_in[1];
    const float* pool = (const float*)d_in[2];
    float* out = (float*)d_out;

    int nb = in_sizes[0] / 8;           // 65536
    int tiles = nb / 128;               // 512

    setup_coef<<<1, 32>>>(conv, pool);
    build_u<<<8, 1024>>>();

    cudaFuncSetAttribute(qgemm, cudaFuncAttributeMaxDynamicSharedMemorySize, SMEM_TOTAL);
    qgemm<<<tiles, 256, SMEM_TOTAL>>>(x, out);
}

// round 7
// speedup vs baseline: 1.6400x; 1.0569x over previous
#include <cuda_runtime.h>
#include <cuda_fp16.h>
#include <cstdint>
#include <math.h>

#define FULL 0xffffffffu

// ===================== device globals =====================
__device__ __half g_Ure[256 * 256];        // U_re[i][k], K-major
__device__ __half g_Uim[256 * 256];        // U_im[i][k], K-major

// ===================== scalar fused-block sim (validated R1/R6) =====================
template<int CB, int TB>
__device__ __forceinline__ void apply_block(float (&re)[8], float (&im)[8],
                                            const float* cf, unsigned lane) {
    float cs = cf[0], ss = cf[1];
    float ar = cf[2], ai = cf[3], br = cf[4], bi = cf[5];
    if constexpr (TB >= 5) {
        static_assert(CB >= 5, "in-lane target gates have in-register control");
        constexpr int tm = 1 << (TB - 5);
#pragma unroll
        for (int r0 = 0; r0 < 8; r0++) {
            if (r0 & tm) continue;
            const int r1 = r0 | tm;
            float x0r = re[r0], x0i = im[r0], x1r = re[r1], x1i = im[r1];
            if (((r0 >> (CB - 5)) & 1) == 0) {
                re[r0] = cs * x0r - ss * x1r;  im[r0] = cs * x0i - ss * x1i;
                re[r1] = ss * x0r + cs * x1r;  im[r1] = ss * x0i + cs * x1i;
            } else {
                re[r0] = -br * x0r + bi * x0i + ar * x1r - ai * x1i;
                im[r0] = -br * x0i - bi * x0r + ar * x1i + ai * x1r;
                re[r1] =  ar * x0r - ai * x0i + br * x1r - bi * x1i;
                im[r1] =  ar * x0i + ai * x0r + br * x1i + bi * x1r;
            }
        }
    } else {
        const bool side = (lane >> TB) & 1;
        if constexpr (CB >= 5) {
            float Bs = side ? ss : -ss;
            float Ar = side ? br : -br;
            float Ai = side ? bi : -bi;
#pragma unroll
            for (int r = 0; r < 8; r++) {
                float pr = __shfl_xor_sync(FULL, re[r], 1 << TB);
                float pi = __shfl_xor_sync(FULL, im[r], 1 << TB);
                if (((r >> (CB - 5)) & 1) == 0) {
                    re[r] = cs * re[r] + Bs * pr;
                    im[r] = cs * im[r] + Bs * pi;
                } else {
                    float xr = re[r], xi = im[r];
                    re[r] = Ar * xr - Ai * xi + ar * pr - ai * pi;
                    im[r] = Ar * xi + Ai * xr + ar * pi + ai * pr;
                }
            }
        } else {
            const bool c = (lane >> CB) & 1;
            float Ar, Ai, Br, Bi;
            if (c) { Ar = side ? br : -br; Ai = side ? bi : -bi; Br = ar; Bi = ai; }
            else   { Ar = cs; Ai = 0.f;    Br = side ? ss : -ss; Bi = 0.f; }
#pragma unroll
            for (int r = 0; r < 8; r++) {
                float pr = __shfl_xor_sync(FULL, re[r], 1 << TB);
                float pi = __shfl_xor_sync(FULL, im[r], 1 << TB);
                float xr = re[r], xi = im[r];
                re[r] = Ar * xr - Ai * xi + Br * pr - Bi * pi;
                im[r] = Ar * xi + Ai * xr + Br * pi + Bi * pr;
            }
        }
    }
}

// build U columns, with coefficient computation fused (smem): warp w -> basis state e_k
__global__ void build_u(const float* __restrict__ conv,
                        const float* __restrict__ pool) {
    __shared__ float scf[21 * 6];
    {
        int t = threadIdx.x;
        if (t < 21) {
            float t0, t1, t2;
            if (t < 14)      { const float* p = conv + t * 3; t0 = p[0]; t1 = p[1]; t2 = p[2]; }
            else if (t < 18) { t0 = pool[0]; t1 = pool[1]; t2 = pool[2]; }
            else if (t < 20) { t0 = pool[3]; t1 = pool[4]; t2 = pool[5]; }
            else             { t0 = pool[6]; t1 = pool[7]; t2 = pool[8]; }
            float sg = 0.5f * (t1 + t2), dl = 0.5f * (t2 - t1);
            float cs = cosf(sg), ss = sinf(sg);
            float cd = cosf(dl), sd = sinf(dl);
            float cp = cosf(t0), sp = sinf(t0);
            float* o = scf + t * 6;
            o[0] = cs; o[1] = ss;
            o[2] = cp * cd; o[3] = sp * cd;
            o[4] = cp * sd; o[5] = sp * sd;
        }
    }
    __syncthreads();

    const int wid = threadIdx.x >> 5;
    const unsigned lane = threadIdx.x & 31;
    const int k = blockIdx.x * (blockDim.x >> 5) + wid;
    float re[8], im[8];
#pragma unroll
    for (int r = 0; r < 8; r++) {
        re[r] = (r == (k >> 5) && lane == (unsigned)(k & 31)) ? 1.f : 0.f;
        im[r] = 0.f;
    }
    apply_block<7, 6>(re, im, scf + 0 * 6, lane);
    apply_block<6, 5>(re, im, scf + 1 * 6, lane);
    apply_block<5, 4>(re, im, scf + 2 * 6, lane);
    apply_block<4, 3>(re, im, scf + 3 * 6, lane);
    apply_block<3, 2>(re, im, scf + 4 * 6, lane);
    apply_block<2, 1>(re, im, scf + 5 * 6, lane);
    apply_block<1, 0>(re, im, scf + 6 * 6, lane);
    apply_block<7, 6>(re, im, scf + 7 * 6, lane);
    apply_block<6, 5>(re, im, scf + 8 * 6, lane);
    apply_block<5, 4>(re, im, scf + 9 * 6, lane);
    apply_block<4, 3>(re, im, scf + 10 * 6, lane);
    apply_block<3, 2>(re, im, scf + 11 * 6, lane);
    apply_block<2, 1>(re, im, scf + 12 * 6, lane);
    apply_block<1, 0>(re, im, scf + 13 * 6, lane);
    apply_block<7, 3>(re, im, scf + 14 * 6, lane);
    apply_block<6, 2>(re, im, scf + 15 * 6, lane);
    apply_block<5, 1>(re, im, scf + 16 * 6, lane);
    apply_block<4, 0>(re, im, scf + 17 * 6, lane);
    apply_block<7, 5>(re, im, scf + 18 * 6, lane);
    apply_block<6, 4>(re, im, scf + 19 * 6, lane);
    apply_block<7, 6>(re, im, scf + 20 * 6, lane);
#pragma unroll
    for (int r = 0; r < 8; r++) {
        int i = (r << 5) | lane;
        g_Ure[i * 256 + k] = __float2half(re[r]);
        g_Uim[i * 256 + k] = __float2half(im[r]);
    }
}

// ===================== HMMA helpers =====================
__device__ __forceinline__ uint32_t smem_u32(const void* p) {
    uint32_t a;
    asm("{ .reg .u64 t; cvta.to.shared.u64 t, %1; cvt.u32.u64 %0, t; }" : "=r"(a) : "l"(p));
    return a;
}
__device__ __forceinline__ void ldsm_x4(uint32_t& r0, uint32_t& r1,
                                        uint32_t& r2, uint32_t& r3, uint32_t addr) {
    asm volatile("ldmatrix.sync.aligned.m8n8.x4.shared.b16 {%0,%1,%2,%3}, [%4];"
                 : "=r"(r0), "=r"(r1), "=r"(r2), "=r"(r3) : "r"(addr));
}
__device__ __forceinline__ void mma16816(float& c0, float& c1, float& c2, float& c3,
                                         uint32_t a0, uint32_t a1, uint32_t a2, uint32_t a3,
                                         uint32_t b0, uint32_t b1) {
    asm volatile("mma.sync.aligned.m16n8k16.row.col.f32.f16.f16.f32 "
                 "{%0,%1,%2,%3}, {%4,%5,%6,%7}, {%8,%9}, {%0,%1,%2,%3};"
                 : "+f"(c0), "+f"(c1), "+f"(c2), "+f"(c3)
                 : "r"(a0), "r"(a1), "r"(a2), "r"(a3), "r"(b0), "r"(b1));
}

// ===================== main GEMM kernel (M=32 per warp) =====================
static constexpr int BROW = 264;                       // halfs per smem row (256 + 8 pad)
static constexpr int SMEM_TOTAL = 128 * BROW * 2;      // 67584 bytes

__global__ void __launch_bounds__(128, 2)
qgemm(const float* __restrict__ x, float* __restrict__ out) {
    extern __shared__ __half smB[];
    const uint32_t smb = smem_u32(smB);
    const int tid  = threadIdx.x;
    const int wid  = tid >> 5;
    const int lane = tid & 31;
    const int quad = lane & 3;       // t%4
    const int qrow = lane >> 2;      // t/4

    // ---- A fragments in registers: 4 row-sels (rows base+qrow+8*rs), 16 k-tiles
    const int base = (blockIdx.x * 4 + wid) * 32;
    uint32_t A2[4][16][2];
#pragma unroll
    for (int rs = 0; rs < 4; rs++) {
        const int row = base + qrow + rs * 8;
        const float4* xp = (const float4*)(x + (size_t)row * 8);
        float4 x0 = xp[0], x1 = xp[1];
        float xv[8] = {x0.x, x0.y, x0.z, x0.w, x1.x, x1.y, x1.z, x1.w};
        float c_[8], s_[8];
#pragma unroll
        for (int q = 0; q < 8; q++) __sincosf(0.5f * xv[q], &s_[q], &c_[q]);
        float hi16[16];
#pragma unroll
        for (int h = 0; h < 16; h++)
            hi16[h] = ((h & 8) ? s_[0] : c_[0]) * ((h & 4) ? s_[1] : c_[1]) *
                      ((h & 2) ? s_[2] : c_[2]) * ((h & 1) ? s_[3] : c_[3]);
        float q5 = (quad & 2) ? s_[5] : c_[5];
        float q6 = (quad & 1) ? s_[6] : c_[6];
        float m56 = q5 * q6;
        float l00 = c_[4] * m56 * c_[7], l01 = c_[4] * m56 * s_[7];
        float l10 = s_[4] * m56 * c_[7], l11 = s_[4] * m56 * s_[7];
#pragma unroll
        for (int kk = 0; kk < 16; kk++) {
            float h = hi16[kk];
            __half2 plo = __floats2half2_rn(h * l00, h * l01);
            __half2 phi = __floats2half2_rn(h * l10, h * l11);
            A2[rs][kk][0] = *(uint32_t*)&plo;
            A2[rs][kk][1] = *(uint32_t*)&phi;
        }
    }

    float z7a[4] = {0,0,0,0}, z4a[4] = {0,0,0,0}, z3a[4] = {0,0,0,0}, z2a[4] = {0,0,0,0};
    float Sa[4] = {0,0,0,0}, z1a[4] = {0,0,0,0}, z0a[4] = {0,0,0,0};

    const int lgrp = lane >> 3, lrow = lane & 7;
    const uint32_t lbase = smb +
        (uint32_t)((((lgrp & 2) ? 64 : 0) + lrow) * BROW + (lgrp & 1) * 8) * 2;

    for (int it = 0; it < 4; it++) {
        const int n0 = it * 64;
        // ---- B chunk: smem rows 0-63 = Ure[n0..], 64-127 = Uim[n0..]; 4096 16B chunks
#pragma unroll
        for (int j = 0; j < 32; j++) {
            int c = j * 128 + tid;
            int row = c >> 5, kc = (c & 31) * 8;
            const __half* src = (row < 64) ? (g_Ure + (size_t)(n0 + row) * 256 + kc)
                                           : (g_Uim + (size_t)(n0 + row - 64) * 256 + kc);
            *(uint4*)(smB + row * BROW + kc) = *(const uint4*)src;
        }
        __syncthreads();

        float Sc[4] = {0,0,0,0};
#pragma unroll
        for (int nt = 0; nt < 8; nt++) {
            float cre[8] = {0,0,0,0,0,0,0,0}, cim[8] = {0,0,0,0,0,0,0,0};
#pragma unroll
            for (int kk = 0; kk < 16; kk++) {
                uint32_t bre0, bre1, bim0, bim1;
                ldsm_x4(bre0, bre1, bim0, bim1,
                        lbase + (uint32_t)(nt * 8 * BROW + kk * 16) * 2);
                mma16816(cre[0], cre[1], cre[2], cre[3],
                         A2[0][kk][0], A2[1][kk][0], A2[0][kk][1], A2[1][kk][1],
                         bre0, bre1);
                mma16816(cre[4], cre[5], cre[6], cre[7],
                         A2[2][kk][0], A2[3][kk][0], A2[2][kk][1], A2[3][kk][1],
                         bre0, bre1);
                mma16816(cim[0], cim[1], cim[2], cim[3],
                         A2[0][kk][0], A2[1][kk][0], A2[0][kk][1], A2[1][kk][1],
                         bim0, bim1);
                mma16816(cim[4], cim[5], cim[6], cim[7],
                         A2[2][kk][0], A2[3][kk][0], A2[2][kk][1], A2[3][kk][1],
                         bim0, bim1);
            }
#pragma unroll
            for (int rs = 0; rs < 4; rs++) {
                float p0 = cre[2*rs] * cre[2*rs] + cim[2*rs] * cim[2*rs];
                float p1 = cre[2*rs+1] * cre[2*rs+1] + cim[2*rs+1] * cim[2*rs+1];
                float d = p0 - p1, s = p0 + p1;
                z7a[rs] += d;
                Sc[rs] += s;
                z4a[rs] += (nt & 1) ? -s : s;
                z3a[rs] += (nt & 2) ? -s : s;
                z2a[rs] += (nt & 4) ? -s : s;
            }
        }
#pragma unroll
        for (int rs = 0; rs < 4; rs++) {
            Sa[rs] += Sc[rs];
            z1a[rs] += (it & 1) ? -Sc[rs] : Sc[rs];
            z0a[rs] += (it & 2) ? -Sc[rs] : Sc[rs];
        }
        __syncthreads();
    }

    // ---- finalize: z6/z5 via lane-constant signs on S; butterfly over quad lanes
#pragma unroll
    for (int rs = 0; rs < 4; rs++) {
        float z[8];
        z[0] = z0a[rs]; z[1] = z1a[rs]; z[2] = z2a[rs]; z[3] = z3a[rs];
        z[4] = z4a[rs];
        z[5] = ((quad >> 1) & 1) ? -Sa[rs] : Sa[rs];
        z[6] = (quad & 1) ? -Sa[rs] : Sa[rs];
        z[7] = z7a[rs];
#pragma unroll
        for (int q = 0; q < 8; q++) {
            z[q] += __shfl_xor_sync(FULL, z[q], 1);
            z[q] += __shfl_xor_sync(FULL, z[q], 2);
        }
        const int row = base + qrow + rs * 8;
        float2* o = (float2*)(out + (size_t)row * 8 + 2 * quad);
        *o = make_float2(z[2 * quad], z[2 * quad + 1]);
    }
}

// ===================== host launcher =====================
extern "C" void kernel_launch(void* const* d_in, const int* in_sizes, int n_in,
                              void* d_out, int out_size) {
    const float* x    = (const float*)d_in[0];
    const float* conv = (const float*)d_in[1];
    const float* pool = (const float*)d_in[2];
    float* out = (float*)d_out;

    int nb = in_sizes[0] / 8;           // 65536
    int tiles = nb / 128;               // 512

    build_u<<<8, 1024>>>(conv, pool);

    cudaFuncSetAttribute(qgemm, cudaFuncAttributeMaxDynamicSharedMemorySize, SMEM_TOTAL);
    qgemm<<<tiles, 128, SMEM_TOTAL>>>(x, out);
}

// round 8
// speedup vs baseline: 2.1180x; 1.2915x over previous
#include <cuda_runtime.h>
#include <cuda_fp16.h>
#include <cstdint>
#include <math.h>

#define FULL 0xffffffffu

// ===================== device globals =====================
__device__ __half g_Ure[256 * 256];        // U_re[i][k], K-major
__device__ __half g_Uim[256 * 256];        // U_im[i][k], K-major

// ===================== scalar fused-block sim (validated R1/R6) =====================
template<int CB, int TB>
__device__ __forceinline__ void apply_block(float (&re)[8], float (&im)[8],
                                            const float* cf, unsigned lane) {
    float cs = cf[0], ss = cf[1];
    float ar = cf[2], ai = cf[3], br = cf[4], bi = cf[5];
    if constexpr (TB >= 5) {
        static_assert(CB >= 5, "in-lane target gates have in-register control");
        constexpr int tm = 1 << (TB - 5);
#pragma unroll
        for (int r0 = 0; r0 < 8; r0++) {
            if (r0 & tm) continue;
            const int r1 = r0 | tm;
            float x0r = re[r0], x0i = im[r0], x1r = re[r1], x1i = im[r1];
            if (((r0 >> (CB - 5)) & 1) == 0) {
                re[r0] = cs * x0r - ss * x1r;  im[r0] = cs * x0i - ss * x1i;
                re[r1] = ss * x0r + cs * x1r;  im[r1] = ss * x0i + cs * x1i;
            } else {
                re[r0] = -br * x0r + bi * x0i + ar * x1r - ai * x1i;
                im[r0] = -br * x0i - bi * x0r + ar * x1i + ai * x1r;
                re[r1] =  ar * x0r - ai * x0i + br * x1r - bi * x1i;
                im[r1] =  ar * x0i + ai * x0r + br * x1i + bi * x1r;
            }
        }
    } else {
        const bool side = (lane >> TB) & 1;
        if constexpr (CB >= 5) {
            float Bs = side ? ss : -ss;
            float Ar = side ? br : -br;
            float Ai = side ? bi : -bi;
#pragma unroll
            for (int r = 0; r < 8; r++) {
                float pr = __shfl_xor_sync(FULL, re[r], 1 << TB);
                float pi = __shfl_xor_sync(FULL, im[r], 1 << TB);
                if (((r >> (CB - 5)) & 1) == 0) {
                    re[r] = cs * re[r] + Bs * pr;
                    im[r] = cs * im[r] + Bs * pi;
                } else {
                    float xr = re[r], xi = im[r];
                    re[r] = Ar * xr - Ai * xi + ar * pr - ai * pi;
                    im[r] = Ar * xi + Ai * xr + ar * pi + ai * pr;
                }
            }
        } else {
            const bool c = (lane >> CB) & 1;
            float Ar, Ai, Br, Bi;
            if (c) { Ar = side ? br : -br; Ai = side ? bi : -bi; Br = ar; Bi = ai; }
            else   { Ar = cs; Ai = 0.f;    Br = side ? ss : -ss; Bi = 0.f; }
#pragma unroll
            for (int r = 0; r < 8; r++) {
                float pr = __shfl_xor_sync(FULL, re[r], 1 << TB);
                float pi = __shfl_xor_sync(FULL, im[r], 1 << TB);
                float xr = re[r], xi = im[r];
                re[r] = Ar * xr - Ai * xi + Br * pr - Bi * pi;
                im[r] = Ar * xi + Ai * xr + Br * pi + Bi * pr;
            }
        }
    }
}

// build U columns (coef computation fused); one warp per basis column
__global__ void build_u(const float* __restrict__ conv,
                        const float* __restrict__ pool) {
    __shared__ float scf[21 * 6];
    {
        int t = threadIdx.x;
        if (t < 21) {
            float t0, t1, t2;
            if (t < 14)      { const float* p = conv + t * 3; t0 = p[0]; t1 = p[1]; t2 = p[2]; }
            else if (t < 18) { t0 = pool[0]; t1 = pool[1]; t2 = pool[2]; }
            else if (t < 20) { t0 = pool[3]; t1 = pool[4]; t2 = pool[5]; }
            else             { t0 = pool[6]; t1 = pool[7]; t2 = pool[8]; }
            float sg = 0.5f * (t1 + t2), dl = 0.5f * (t2 - t1);
            float cs = cosf(sg), ss = sinf(sg);
            float cd = cosf(dl), sd = sinf(dl);
            float cp = cosf(t0), sp = sinf(t0);
            float* o = scf + t * 6;
            o[0] = cs; o[1] = ss;
            o[2] = cp * cd; o[3] = sp * cd;
            o[4] = cp * sd; o[5] = sp * sd;
        }
    }
    __syncthreads();

    const int wid = threadIdx.x >> 5;
    const unsigned lane = threadIdx.x & 31;
    const int k = blockIdx.x * (blockDim.x >> 5) + wid;
    float re[8], im[8];
#pragma unroll
    for (int r = 0; r < 8; r++) {
        re[r] = (r == (k >> 5) && lane == (unsigned)(k & 31)) ? 1.f : 0.f;
        im[r] = 0.f;
    }
    apply_block<7, 6>(re, im, scf + 0 * 6, lane);
    apply_block<6, 5>(re, im, scf + 1 * 6, lane);
    apply_block<5, 4>(re, im, scf + 2 * 6, lane);
    apply_block<4, 3>(re, im, scf + 3 * 6, lane);
    apply_block<3, 2>(re, im, scf + 4 * 6, lane);
    apply_block<2, 1>(re, im, scf + 5 * 6, lane);
    apply_block<1, 0>(re, im, scf + 6 * 6, lane);
    apply_block<7, 6>(re, im, scf + 7 * 6, lane);
    apply_block<6, 5>(re, im, scf + 8 * 6, lane);
    apply_block<5, 4>(re, im, scf + 9 * 6, lane);
    apply_block<4, 3>(re, im, scf + 10 * 6, lane);
    apply_block<3, 2>(re, im, scf + 11 * 6, lane);
    apply_block<2, 1>(re, im, scf + 12 * 6, lane);
    apply_block<1, 0>(re, im, scf + 13 * 6, lane);
    apply_block<7, 3>(re, im, scf + 14 * 6, lane);
    apply_block<6, 2>(re, im, scf + 15 * 6, lane);
    apply_block<5, 1>(re, im, scf + 16 * 6, lane);
    apply_block<4, 0>(re, im, scf + 17 * 6, lane);
    apply_block<7, 5>(re, im, scf + 18 * 6, lane);
    apply_block<6, 4>(re, im, scf + 19 * 6, lane);
    apply_block<7, 6>(re, im, scf + 20 * 6, lane);
#pragma unroll
    for (int r = 0; r < 8; r++) {
        int i = (r << 5) | lane;
        g_Ure[i * 256 + k] = __float2half(re[r]);
        g_Uim[i * 256 + k] = __float2half(im[r]);
    }
}

// ===================== HMMA helpers =====================
__device__ __forceinline__ uint32_t smem_u32(const void* p) {
    uint32_t a;
    asm("{ .reg .u64 t; cvta.to.shared.u64 t, %1; cvt.u32.u64 %0, t; }" : "=r"(a) : "l"(p));
    return a;
}
__device__ __forceinline__ void ldsm_x4(uint32_t& r0, uint32_t& r1,
                                        uint32_t& r2, uint32_t& r3, uint32_t addr) {
    asm volatile("ldmatrix.sync.aligned.m8n8.x4.shared.b16 {%0,%1,%2,%3}, [%4];"
                 : "=r"(r0), "=r"(r1), "=r"(r2), "=r"(r3) : "r"(addr));
}
__device__ __forceinline__ void mma16816(float& c0, float& c1, float& c2, float& c3,
                                         uint32_t a0, uint32_t a1, uint32_t a2, uint32_t a3,
                                         uint32_t b0, uint32_t b1) {
    asm volatile("mma.sync.aligned.m16n8k16.row.col.f32.f16.f16.f32 "
                 "{%0,%1,%2,%3}, {%4,%5,%6,%7}, {%8,%9}, {%0,%1,%2,%3};"
                 : "+f"(c0), "+f"(c1), "+f"(c2), "+f"(c3)
                 : "r"(a0), "r"(a1), "r"(a2), "r"(a3), "r"(b0), "r"(b1));
}

// ===================== main GEMM kernel (M=32 per warp, split-K ILP) =====================
static constexpr int BROW = 264;                       // halfs per smem row (256 + 8 pad)
static constexpr int SMEM_TOTAL = 128 * BROW * 2;      // 67584 bytes

__global__ void __launch_bounds__(128, 2)
qgemm(const float* __restrict__ x, float* __restrict__ out) {
    extern __shared__ __half smB[];
    const uint32_t smb = smem_u32(smB);
    const int tid  = threadIdx.x;
    const int wid  = tid >> 5;
    const int lane = tid & 31;
    const int quad = lane & 3;       // t%4
    const int qrow = lane >> 2;      // t/4

    // ---- A fragments in registers: 4 row-sels (rows base+qrow+8*rs), 16 k-tiles
    const int base = (blockIdx.x * 4 + wid) * 32;
    uint32_t A2[4][16][2];
#pragma unroll
    for (int rs = 0; rs < 4; rs++) {
        const int row = base + qrow + rs * 8;
        const float4* xp = (const float4*)(x + (size_t)row * 8);
        float4 x0 = xp[0], x1 = xp[1];
        float xv[8] = {x0.x, x0.y, x0.z, x0.w, x1.x, x1.y, x1.z, x1.w};
        float c_[8], s_[8];
#pragma unroll
        for (int q = 0; q < 8; q++) __sincosf(0.5f * xv[q], &s_[q], &c_[q]);
        float hi16[16];
#pragma unroll
        for (int h = 0; h < 16; h++)
            hi16[h] = ((h & 8) ? s_[0] : c_[0]) * ((h & 4) ? s_[1] : c_[1]) *
                      ((h & 2) ? s_[2] : c_[2]) * ((h & 1) ? s_[3] : c_[3]);
        float q5 = (quad & 2) ? s_[5] : c_[5];
        float q6 = (quad & 1) ? s_[6] : c_[6];
        float m56 = q5 * q6;
        float l00 = c_[4] * m56 * c_[7], l01 = c_[4] * m56 * s_[7];
        float l10 = s_[4] * m56 * c_[7], l11 = s_[4] * m56 * s_[7];
#pragma unroll
        for (int kk = 0; kk < 16; kk++) {
            float h = hi16[kk];
            __half2 plo = __floats2half2_rn(h * l00, h * l01);
            __half2 phi = __floats2half2_rn(h * l10, h * l11);
            A2[rs][kk][0] = *(uint32_t*)&plo;
            A2[rs][kk][1] = *(uint32_t*)&phi;
        }
    }

    float z7a[4] = {0,0,0,0}, z4a[4] = {0,0,0,0}, z3a[4] = {0,0,0,0}, z2a[4] = {0,0,0,0};
    float Sa[4] = {0,0,0,0}, z1a[4] = {0,0,0,0}, z0a[4] = {0,0,0,0};

    const int lgrp = lane >> 3, lrow = lane & 7;
    const uint32_t lbase = smb +
        (uint32_t)((((lgrp & 2) ? 64 : 0) + lrow) * BROW + (lgrp & 1) * 8) * 2;

    for (int it = 0; it < 4; it++) {
        const int n0 = it * 64;
        // ---- B chunk: smem rows 0-63 = Ure[n0..], 64-127 = Uim[n0..]
#pragma unroll
        for (int j = 0; j < 32; j++) {
            int c = j * 128 + tid;
            int row = c >> 5, kc = (c & 31) * 8;
            const __half* src = (row < 64) ? (g_Ure + (size_t)(n0 + row) * 256 + kc)
                                           : (g_Uim + (size_t)(n0 + row - 64) * 256 + kc);
            *(uint4*)(smB + row * BROW + kc) = *(const uint4*)src;
        }
        __syncthreads();

        float Sc[4] = {0,0,0,0};
#pragma unroll
        for (int nt = 0; nt < 8; nt++) {
            // split-K accumulators: even kk -> *_e, odd kk -> *_o  (8 indep chains)
            float cre_e[8] = {0,0,0,0,0,0,0,0}, cim_e[8] = {0,0,0,0,0,0,0,0};
            float cre_o[8] = {0,0,0,0,0,0,0,0}, cim_o[8] = {0,0,0,0,0,0,0,0};
            uint32_t bufA[4], bufB[4];
            ldsm_x4(bufA[0], bufA[1], bufA[2], bufA[3],
                    lbase + (uint32_t)(nt * 8 * BROW) * 2);
#pragma unroll
            for (int kk = 0; kk < 16; kk++) {
                uint32_t* cur = (kk & 1) ? bufB : bufA;
                uint32_t* nxt = (kk & 1) ? bufA : bufB;
                if (kk < 15)
                    ldsm_x4(nxt[0], nxt[1], nxt[2], nxt[3],
                            lbase + (uint32_t)(nt * 8 * BROW + (kk + 1) * 16) * 2);
                float* cr = (kk & 1) ? cre_o : cre_e;
                float* ci = (kk & 1) ? cim_o : cim_e;
                mma16816(cr[0], cr[1], cr[2], cr[3],
                         A2[0][kk][0], A2[1][kk][0], A2[0][kk][1], A2[1][kk][1],
                         cur[0], cur[1]);
                mma16816(cr[4], cr[5], cr[6], cr[7],
                         A2[2][kk][0], A2[3][kk][0], A2[2][kk][1], A2[3][kk][1],
                         cur[0], cur[1]);
                mma16816(ci[0], ci[1], ci[2], ci[3],
                         A2[0][kk][0], A2[1][kk][0], A2[0][kk][1], A2[1][kk][1],
                         cur[2], cur[3]);
                mma16816(ci[4], ci[5], ci[6], ci[7],
                         A2[2][kk][0], A2[3][kk][0], A2[2][kk][1], A2[3][kk][1],
                         cur[2], cur[3]);
            }
#pragma unroll
            for (int rs = 0; rs < 4; rs++) {
                float r0 = cre_e[2*rs]   + cre_o[2*rs];
                float r1 = cre_e[2*rs+1] + cre_o[2*rs+1];
                float i0 = cim_e[2*rs]   + cim_o[2*rs];
                float i1 = cim_e[2*rs+1] + cim_o[2*rs+1];
                float p0 = r0 * r0 + i0 * i0;
                float p1 = r1 * r1 + i1 * i1;
                float d = p0 - p1, s = p0 + p1;
                z7a[rs] += d;
                Sc[rs] += s;
                z4a[rs] += (nt & 1) ? -s : s;
                z3a[rs] += (nt & 2) ? -s : s;
                z2a[rs] += (nt & 4) ? -s : s;
            }
        }
#pragma unroll
        for (int rs = 0; rs < 4; rs++) {
            Sa[rs] += Sc[rs];
            z1a[rs] += (it & 1) ? -Sc[rs] : Sc[rs];
            z0a[rs] += (it & 2) ? -Sc[rs] : Sc[rs];
        }
        __syncthreads();
    }

    // ---- finalize: z6/z5 via lane-constant signs on S; butterfly over quad lanes
#pragma unroll
    for (int rs = 0; rs < 4; rs++) {
        float z[8];
        z[0] = z0a[rs]; z[1] = z1a[rs]; z[2] = z2a[rs]; z[3] = z3a[rs];
        z[4] = z4a[rs];
        z[5] = ((quad >> 1) & 1) ? -Sa[rs] : Sa[rs];
        z[6] = (quad & 1) ? -Sa[rs] : Sa[rs];
        z[7] = z7a[rs];
#pragma unroll
        for (int q = 0; q < 8; q++) {
            z[q] += __shfl_xor_sync(FULL, z[q], 1);
            z[q] += __shfl_xor_sync(FULL, z[q], 2);
        }
        const int row = base + qrow + rs * 8;
        float2* o = (float2*)(out + (size_t)row * 8 + 2 * quad);
        *o = make_float2(z[2 * quad], z[2 * quad + 1]);
    }
}

// ===================== host launcher =====================
extern "C" void kernel_launch(void* const* d_in, const int* in_sizes, int n_in,
                              void* d_out, int out_size) {
    const float* x    = (const float*)d_in[0];
    const float* conv = (const float*)d_in[1];
    const float* pool = (const float*)d_in[2];
    float* out = (float*)d_out;

    int nb = in_sizes[0] / 8;           // 65536
    int tiles = nb / 128;               // 512

    build_u<<<64, 128>>>(conv, pool);   // one warp per U column, spread over 64 SMs

    cudaFuncSetAttribute(qgemm, cudaFuncAttributeMaxDynamicSharedMemorySize, SMEM_TOTAL);
    qgemm<<<tiles, 128, SMEM_TOTAL>>>(x, out);
}

// round 9
// speedup vs baseline: 2.1801x; 1.0293x over previous
#include <cuda_runtime.h>
#include <cuda_fp16.h>
#include <cstdint>
#include <math.h>

#define FULL 0xffffffffu

// ===================== device globals =====================
__device__ __half g_Ure[256 * 256];        // U_re[i][k], K-major
__device__ __half g_Uim[256 * 256];        // U_im[i][k], K-major

// ===================== scalar fused-block sim (validated R1/R6) =====================
template<int CB, int TB>
__device__ __forceinline__ void apply_block(float (&re)[8], float (&im)[8],
                                            const float* cf, unsigned lane) {
    float cs = cf[0], ss = cf[1];
    float ar = cf[2], ai = cf[3], br = cf[4], bi = cf[5];
    if constexpr (TB >= 5) {
        static_assert(CB >= 5, "in-lane target gates have in-register control");
        constexpr int tm = 1 << (TB - 5);
#pragma unroll
        for (int r0 = 0; r0 < 8; r0++) {
            if (r0 & tm) continue;
            const int r1 = r0 | tm;
            float x0r = re[r0], x0i = im[r0], x1r = re[r1], x1i = im[r1];
            if (((r0 >> (CB - 5)) & 1) == 0) {
                re[r0] = cs * x0r - ss * x1r;  im[r0] = cs * x0i - ss * x1i;
                re[r1] = ss * x0r + cs * x1r;  im[r1] = ss * x0i + cs * x1i;
            } else {
                re[r0] = -br * x0r + bi * x0i + ar * x1r - ai * x1i;
                im[r0] = -br * x0i - bi * x0r + ar * x1i + ai * x1r;
                re[r1] =  ar * x0r - ai * x0i + br * x1r - bi * x1i;
                im[r1] =  ar * x0i + ai * x0r + br * x1i + bi * x1r;
            }
        }
    } else {
        const bool side = (lane >> TB) & 1;
        if constexpr (CB >= 5) {
            float Bs = side ? ss : -ss;
            float Ar = side ? br : -br;
            float Ai = side ? bi : -bi;
#pragma unroll
            for (int r = 0; r < 8; r++) {
                float pr = __shfl_xor_sync(FULL, re[r], 1 << TB);
                float pi = __shfl_xor_sync(FULL, im[r], 1 << TB);
                if (((r >> (CB - 5)) & 1) == 0) {
                    re[r] = cs * re[r] + Bs * pr;
                    im[r] = cs * im[r] + Bs * pi;
                } else {
                    float xr = re[r], xi = im[r];
                    re[r] = Ar * xr - Ai * xi + ar * pr - ai * pi;
                    im[r] = Ar * xi + Ai * xr + ar * pi + ai * pr;
                }
            }
        } else {
            const bool c = (lane >> CB) & 1;
            float Ar, Ai, Br, Bi;
            if (c) { Ar = side ? br : -br; Ai = side ? bi : -bi; Br = ar; Bi = ai; }
            else   { Ar = cs; Ai = 0.f;    Br = side ? ss : -ss; Bi = 0.f; }
#pragma unroll
            for (int r = 0; r < 8; r++) {
                float pr = __shfl_xor_sync(FULL, re[r], 1 << TB);
                float pi = __shfl_xor_sync(FULL, im[r], 1 << TB);
                float xr = re[r], xi = im[r];
                re[r] = Ar * xr - Ai * xi + Br * pr - Bi * pi;
                im[r] = Ar * xi + Ai * xr + Br * pi + Bi * pr;
            }
        }
    }
}

// build U columns (coef computation fused); one warp per basis column
__global__ void build_u(const float* __restrict__ conv,
                        const float* __restrict__ pool) {
    __shared__ float scf[21 * 6];
    {
        int t = threadIdx.x;
        if (t < 21) {
            float t0, t1, t2;
            if (t < 14)      { const float* p = conv + t * 3; t0 = p[0]; t1 = p[1]; t2 = p[2]; }
            else if (t < 18) { t0 = pool[0]; t1 = pool[1]; t2 = pool[2]; }
            else if (t < 20) { t0 = pool[3]; t1 = pool[4]; t2 = pool[5]; }
            else             { t0 = pool[6]; t1 = pool[7]; t2 = pool[8]; }
            float sg = 0.5f * (t1 + t2), dl = 0.5f * (t2 - t1);
            float cs = cosf(sg), ss = sinf(sg);
            float cd = cosf(dl), sd = sinf(dl);
            float cp = cosf(t0), sp = sinf(t0);
            float* o = scf + t * 6;
            o[0] = cs; o[1] = ss;
            o[2] = cp * cd; o[3] = sp * cd;
            o[4] = cp * sd; o[5] = sp * sd;
        }
    }
    __syncthreads();

    const int wid = threadIdx.x >> 5;
    const unsigned lane = threadIdx.x & 31;
    const int k = blockIdx.x * (blockDim.x >> 5) + wid;
    float re[8], im[8];
#pragma unroll
    for (int r = 0; r < 8; r++) {
        re[r] = (r == (k >> 5) && lane == (unsigned)(k & 31)) ? 1.f : 0.f;
        im[r] = 0.f;
    }
    apply_block<7, 6>(re, im, scf + 0 * 6, lane);
    apply_block<6, 5>(re, im, scf + 1 * 6, lane);
    apply_block<5, 4>(re, im, scf + 2 * 6, lane);
    apply_block<4, 3>(re, im, scf + 3 * 6, lane);
    apply_block<3, 2>(re, im, scf + 4 * 6, lane);
    apply_block<2, 1>(re, im, scf + 5 * 6, lane);
    apply_block<1, 0>(re, im, scf + 6 * 6, lane);
    apply_block<7, 6>(re, im, scf + 7 * 6, lane);
    apply_block<6, 5>(re, im, scf + 8 * 6, lane);
    apply_block<5, 4>(re, im, scf + 9 * 6, lane);
    apply_block<4, 3>(re, im, scf + 10 * 6, lane);
    apply_block<3, 2>(re, im, scf + 11 * 6, lane);
    apply_block<2, 1>(re, im, scf + 12 * 6, lane);
    apply_block<1, 0>(re, im, scf + 13 * 6, lane);
    apply_block<7, 3>(re, im, scf + 14 * 6, lane);
    apply_block<6, 2>(re, im, scf + 15 * 6, lane);
    apply_block<5, 1>(re, im, scf + 16 * 6, lane);
    apply_block<4, 0>(re, im, scf + 17 * 6, lane);
    apply_block<7, 5>(re, im, scf + 18 * 6, lane);
    apply_block<6, 4>(re, im, scf + 19 * 6, lane);
    apply_block<7, 6>(re, im, scf + 20 * 6, lane);
#pragma unroll
    for (int r = 0; r < 8; r++) {
        int i = (r << 5) | lane;
        g_Ure[i * 256 + k] = __float2half(re[r]);
        g_Uim[i * 256 + k] = __float2half(im[r]);
    }
}

// ===================== HMMA helpers =====================
__device__ __forceinline__ uint32_t smem_u32(const void* p) {
    uint32_t a;
    asm("{ .reg .u64 t; cvta.to.shared.u64 t, %1; cvt.u32.u64 %0, t; }" : "=r"(a) : "l"(p));
    return a;
}
__device__ __forceinline__ void ldsm_x4(uint32_t& r0, uint32_t& r1,
                                        uint32_t& r2, uint32_t& r3, uint32_t addr) {
    asm volatile("ldmatrix.sync.aligned.m8n8.x4.shared.b16 {%0,%1,%2,%3}, [%4];"
                 : "=r"(r0), "=r"(r1), "=r"(r2), "=r"(r3) : "r"(addr));
}
// fp16-accumulate MMA: D(2xf16x2) = A*B + D
__device__ __forceinline__ void mma16816h(uint32_t& d0, uint32_t& d1,
                                          uint32_t a0, uint32_t a1, uint32_t a2, uint32_t a3,
                                          uint32_t b0, uint32_t b1) {
    asm volatile("mma.sync.aligned.m16n8k16.row.col.f16.f16.f16.f16 "
                 "{%0,%1}, {%2,%3,%4,%5}, {%6,%7}, {%0,%1};"
                 : "+r"(d0), "+r"(d1)
                 : "r"(a0), "r"(a1), "r"(a2), "r"(a3), "r"(b0), "r"(b1));
}
__device__ __forceinline__ uint32_t hadd2u(uint32_t a, uint32_t b) {
    uint32_t d; asm("add.rn.f16x2 %0,%1,%2;" : "=r"(d) : "r"(a), "r"(b)); return d;
}

// ===================== main GEMM kernel (M=32/warp, f16 accum, split-K4) =====================
static constexpr int BROW = 264;                       // halfs per smem row (256 + 8 pad)
static constexpr int SMEM_TOTAL = 128 * BROW * 2;      // 67584 bytes

__global__ void __launch_bounds__(128, 2)
qgemm(const float* __restrict__ x, float* __restrict__ out) {
    extern __shared__ __half smB[];
    const uint32_t smb = smem_u32(smB);
    const int tid  = threadIdx.x;
    const int wid  = tid >> 5;
    const int lane = tid & 31;
    const int quad = lane & 3;       // t%4
    const int qrow = lane >> 2;      // t/4

    // ---- A fragments in registers: 4 row-sels (rows base+qrow+8*rs), 16 k-tiles
    const int base = (blockIdx.x * 4 + wid) * 32;
    uint32_t A2[4][16][2];
#pragma unroll
    for (int rs = 0; rs < 4; rs++) {
        const int row = base + qrow + rs * 8;
        const float4* xp = (const float4*)(x + (size_t)row * 8);
        float4 x0 = xp[0], x1 = xp[1];
        float xv[8] = {x0.x, x0.y, x0.z, x0.w, x1.x, x1.y, x1.z, x1.w};
        float c_[8], s_[8];
#pragma unroll
        for (int q = 0; q < 8; q++) __sincosf(0.5f * xv[q], &s_[q], &c_[q]);
        float hi16[16];
#pragma unroll
        for (int h = 0; h < 16; h++)
            hi16[h] = ((h & 8) ? s_[0] : c_[0]) * ((h & 4) ? s_[1] : c_[1]) *
                      ((h & 2) ? s_[2] : c_[2]) * ((h & 1) ? s_[3] : c_[3]);
        float q5 = (quad & 2) ? s_[5] : c_[5];
        float q6 = (quad & 1) ? s_[6] : c_[6];
        float m56 = q5 * q6;
        float l00 = c_[4] * m56 * c_[7], l01 = c_[4] * m56 * s_[7];
        float l10 = s_[4] * m56 * c_[7], l11 = s_[4] * m56 * s_[7];
#pragma unroll
        for (int kk = 0; kk < 16; kk++) {
            float h = hi16[kk];
            __half2 plo = __floats2half2_rn(h * l00, h * l01);
            __half2 phi = __floats2half2_rn(h * l10, h * l11);
            A2[rs][kk][0] = *(uint32_t*)&plo;
            A2[rs][kk][1] = *(uint32_t*)&phi;
        }
    }

    float z7a[4] = {0,0,0,0}, z4a[4] = {0,0,0,0}, z3a[4] = {0,0,0,0}, z2a[4] = {0,0,0,0};
    float Sa[4] = {0,0,0,0}, z1a[4] = {0,0,0,0}, z0a[4] = {0,0,0,0};

    const int lgrp = lane >> 3, lrow = lane & 7;
    const uint32_t lbase = smb +
        (uint32_t)((((lgrp & 2) ? 64 : 0) + lrow) * BROW + (lgrp & 1) * 8) * 2;

    for (int it = 0; it < 4; it++) {
        const int n0 = it * 64;
        // ---- B chunk: smem rows 0-63 = Ure[n0..], 64-127 = Uim[n0..]
#pragma unroll
        for (int j = 0; j < 32; j++) {
            int c = j * 128 + tid;
            int row = c >> 5, kc = (c & 31) * 8;
            const __half* src = (row < 64) ? (g_Ure + (size_t)(n0 + row) * 256 + kc)
                                           : (g_Uim + (size_t)(n0 + row - 64) * 256 + kc);
            *(uint4*)(smB + row * BROW + kc) = *(const uint4*)src;
        }
        __syncthreads();

        float Sc[4] = {0,0,0,0};
#pragma unroll
        for (int nt = 0; nt < 8; nt++) {
            // f16 accumulators: [mg][chain][reg]; mg: 0=re rs01, 1=re rs23, 2=im rs01, 3=im rs23
            uint32_t acc[4][4][2];
#pragma unroll
            for (int mg = 0; mg < 4; mg++)
#pragma unroll
                for (int ch = 0; ch < 4; ch++) { acc[mg][ch][0] = 0u; acc[mg][ch][1] = 0u; }

            uint32_t bufA[4], bufB[4];
            ldsm_x4(bufA[0], bufA[1], bufA[2], bufA[3],
                    lbase + (uint32_t)(nt * 8 * BROW) * 2);
#pragma unroll
            for (int kk = 0; kk < 16; kk++) {
                uint32_t* cur = (kk & 1) ? bufB : bufA;
                uint32_t* nxt = (kk & 1) ? bufA : bufB;
                if (kk < 15)
                    ldsm_x4(nxt[0], nxt[1], nxt[2], nxt[3],
                            lbase + (uint32_t)(nt * 8 * BROW + (kk + 1) * 16) * 2);
                const int ch = kk & 3;
                mma16816h(acc[0][ch][0], acc[0][ch][1],
                          A2[0][kk][0], A2[1][kk][0], A2[0][kk][1], A2[1][kk][1],
                          cur[0], cur[1]);
                mma16816h(acc[1][ch][0], acc[1][ch][1],
                          A2[2][kk][0], A2[3][kk][0], A2[2][kk][1], A2[3][kk][1],
                          cur[0], cur[1]);
                mma16816h(acc[2][ch][0], acc[2][ch][1],
                          A2[0][kk][0], A2[1][kk][0], A2[0][kk][1], A2[1][kk][1],
                          cur[2], cur[3]);
                mma16816h(acc[3][ch][0], acc[3][ch][1],
                          A2[2][kk][0], A2[3][kk][0], A2[2][kk][1], A2[3][kk][1],
                          cur[2], cur[3]);
            }
            // combine chains (f16x2 adds), then promote to fp32 in the |.|^2 epilogue
            uint32_t res[4][2];
#pragma unroll
            for (int mg = 0; mg < 4; mg++)
#pragma unroll
                for (int r = 0; r < 2; r++)
                    res[mg][r] = hadd2u(hadd2u(acc[mg][0][r], acc[mg][1][r]),
                                        hadd2u(acc[mg][2][r], acc[mg][3][r]));
#pragma unroll
            for (int rs = 0; rs < 4; rs++) {
                const int mg = rs >> 1, r = rs & 1;
                float2 fr = __half22float2(*(__half2*)&res[mg][r]);
                float2 fi = __half22float2(*(__half2*)&res[mg + 2][r]);
                float p0 = fr.x * fr.x + fi.x * fi.x;
                float p1 = fr.y * fr.y + fi.y * fi.y;
                float d = p0 - p1, s = p0 + p1;
                z7a[rs] += d;
                Sc[rs] += s;
                z4a[rs] += (nt & 1) ? -s : s;
                z3a[rs] += (nt & 2) ? -s : s;
                z2a[rs] += (nt & 4) ? -s : s;
            }
        }
#pragma unroll
        for (int rs = 0; rs < 4; rs++) {
            Sa[rs] += Sc[rs];
            z1a[rs] += (it & 1) ? -Sc[rs] : Sc[rs];
            z0a[rs] += (it & 2) ? -Sc[rs] : Sc[rs];
        }
        __syncthreads();
    }

    // ---- finalize: z6/z5 via lane-constant signs on S; butterfly over quad lanes
#pragma unroll
    for (int rs = 0; rs < 4; rs++) {
        float z[8];
        z[0] = z0a[rs]; z[1] = z1a[rs]; z[2] = z2a[rs]; z[3] = z3a[rs];
        z[4] = z4a[rs];
        z[5] = ((quad >> 1) & 1) ? -Sa[rs] : Sa[rs];
        z[6] = (quad & 1) ? -Sa[rs] : Sa[rs];
        z[7] = z7a[rs];
#pragma unroll
        for (int q = 0; q < 8; q++) {
            z[q] += __shfl_xor_sync(FULL, z[q], 1);
            z[q] += __shfl_xor_sync(FULL, z[q], 2);
        }
        const int row = base + qrow + rs * 8;
        float2* o = (float2*)(out + (size_t)row * 8 + 2 * quad);
        *o = make_float2(z[2 * quad], z[2 * quad + 1]);
    }
}

// ===================== host launcher =====================
extern "C" void kernel_launch(void* const* d_in, const int* in_sizes, int n_in,
                              void* d_out, int out_size) {
    const float* x    = (const float*)d_in[0];
    const float* conv = (const float*)d_in[1];
    const float* pool = (const float*)d_in[2];
    float* out = (float*)d_out;

    int nb = in_sizes[0] / 8;           // 65536
    int tiles = nb / 128;               // 512

    build_u<<<128, 64>>>(conv, pool);   // 256 warps over 128 SMs, 1 wave

    cudaFuncSetAttribute(qgemm, cudaFuncAttributeMaxDynamicSharedMemorySize, SMEM_TOTAL);
    qgemm<<<tiles, 128, SMEM_TOTAL>>>(x, out);
}